// round 4
// baseline (speedup 1.0000x reference)
#include <cuda_runtime.h>
#include <cstdint>

using ull = unsigned long long;

static constexpr int D = 256, H = 512, NCLS = 10, TPTS = 8;
static constexpr int ROWS = 16, THREADS = 256, KC = 16;
static constexpr int BUFSZ = KC * H;                    // 8192 floats
static constexpr int OFF_Y = 0;
static constexpr int OFF_YS = ROWS * D;                 // 4096
static constexpr int OFF_H  = OFF_YS + ROWS * D;        // 8192
static constexpr int OFF_W  = OFF_H + ROWS * H;         // 16384
static constexpr int SMEM_FLOATS = OFF_W + 3 * BUFSZ;   // 40960 -> 160 KB
static constexpr int SMEM_BYTES  = SMEM_FLOATS * 4;

__device__ __forceinline__ ull fma2(ull a, ull b, ull c) {
    ull d; asm("fma.rn.f32x2 %0, %1, %2, %3;" : "=l"(d) : "l"(a), "l"(b), "l"(c)); return d;
}
__device__ __forceinline__ ull pack2(float x) {
    ull r; asm("mov.b64 %0, {%1, %1};" : "=l"(r) : "f"(x)); return r;
}
__device__ __forceinline__ float2 u2f(ull v) {
    float2 r; asm("mov.b64 {%0, %1}, %2;" : "=f"(r.x), "=f"(r.y) : "l"(v)); return r;
}
__device__ __forceinline__ float tanhfast(float x) {
    float e = __expf(2.0f * x);
    return 1.0f - __fdividef(2.0f, e + 1.0f);
}
__device__ __forceinline__ void cp16(float* smdst, const float* gsrc) {
    unsigned sa = (unsigned)__cvta_generic_to_shared(smdst);
    asm volatile("cp.async.cg.shared.global [%0], [%1], 16;" :: "r"(sa), "l"(gsrc) : "memory");
}
__device__ __forceinline__ void cpcommit() { asm volatile("cp.async.commit_group;" ::: "memory"); }
__device__ __forceinline__ void cpwait1()  { asm volatile("cp.async.wait_group 1;" ::: "memory"); }

template <int N4>
__device__ __forceinline__ void copy_chunk(float* dst, const float* src, int tid) {
#pragma unroll
    for (int i = 0; i < N4 / THREADS; i++) {
        int idx = tid + i * THREADS;
        cp16(dst + idx * 4, src + idx * 4);
    }
}

// GEMM1: h = tanh(ysrc[16xD] @ W1[DxH] + b1); thread owns rows r0..r0+3,
// cols {c0..c0+3} U {c0+256..c0+259}.
__device__ __forceinline__ void gemm1(const float* ysrc, const float* gW1,
                                      float* hsm, float* wb, const float (&b1r)[8],
                                      int tid, int r0, int c0) {
    constexpr int NCH = D / KC;            // 16
    constexpr int N4  = KC * H / 4;        // 2048
    copy_chunk<N4>(wb, gW1, tid);                      cpcommit();
    copy_chunk<N4>(wb + BUFSZ, gW1 + KC * H, tid);     cpcommit();
    ull acc[4][4];
#pragma unroll
    for (int i = 0; i < 4; i++)
#pragma unroll
        for (int p = 0; p < 4; p++) acc[i][p] = 0ULL;

    for (int ch = 0; ch < NCH; ch++) {
        cpwait1(); __syncthreads();
        const float* wrb = wb + (ch % 3) * BUFSZ;
        const int kb = ch * KC;
#pragma unroll
        for (int k4 = 0; k4 < KC; k4 += 4) {
            float4 av[4];
#pragma unroll
            for (int i = 0; i < 4; i++) av[i] = *(const float4*)&ysrc[(r0 + i) * D + kb + k4];
            float ax[4][4];
#pragma unroll
            for (int i = 0; i < 4; i++) {
                ax[i][0] = av[i].x; ax[i][1] = av[i].y; ax[i][2] = av[i].z; ax[i][3] = av[i].w;
            }
#pragma unroll
            for (int kk = 0; kk < 4; kk++) {
                const float* wr = wrb + (k4 + kk) * H;
                ulonglong2 wA = *(const ulonglong2*)(wr + c0);
                ulonglong2 wB = *(const ulonglong2*)(wr + c0 + 256);
#pragma unroll
                for (int i = 0; i < 4; i++) {
                    ull a2 = pack2(ax[i][kk]);
                    acc[i][0] = fma2(a2, wA.x, acc[i][0]);
                    acc[i][1] = fma2(a2, wA.y, acc[i][1]);
                    acc[i][2] = fma2(a2, wB.x, acc[i][2]);
                    acc[i][3] = fma2(a2, wB.y, acc[i][3]);
                }
            }
        }
        if (ch + 2 < NCH) copy_chunk<N4>(wb + ((ch + 2) % 3) * BUFSZ, gW1 + (ch + 2) * KC * H, tid);
        cpcommit();
    }
#pragma unroll
    for (int i = 0; i < 4; i++) {
        float2 f0 = u2f(acc[i][0]), f1 = u2f(acc[i][1]);
        float2 f2 = u2f(acc[i][2]), f3 = u2f(acc[i][3]);
        float4 o1, o2;
        o1.x = tanhfast(f0.x + b1r[0]); o1.y = tanhfast(f0.y + b1r[1]);
        o1.z = tanhfast(f1.x + b1r[2]); o1.w = tanhfast(f1.y + b1r[3]);
        o2.x = tanhfast(f2.x + b1r[4]); o2.y = tanhfast(f2.y + b1r[5]);
        o2.z = tanhfast(f3.x + b1r[6]); o2.w = tanhfast(f3.y + b1r[7]);
        *(float4*)&hsm[(r0 + i) * H + c0]       = o1;
        *(float4*)&hsm[(r0 + i) * H + c0 + 256] = o2;
    }
}

// GEMM2: k = h[16xH] @ W2[HxD] + b2; result stays in acc (thread owns rows
// r0..r0+3, cols c0..c0+3).
__device__ __forceinline__ void gemm2(const float* hsm, const float* gW2, float* wb,
                                      ull (&acc)[4][2], ulonglong2 b2p,
                                      int tid, int r0, int c0) {
    constexpr int NCH = H / KC;            // 32
    constexpr int N4  = KC * D / 4;        // 1024
    copy_chunk<N4>(wb, gW2, tid);                      cpcommit();
    copy_chunk<N4>(wb + BUFSZ, gW2 + KC * D, tid);     cpcommit();
#pragma unroll
    for (int i = 0; i < 4; i++) { acc[i][0] = b2p.x; acc[i][1] = b2p.y; }

    for (int ch = 0; ch < NCH; ch++) {
        cpwait1(); __syncthreads();
        const float* wrb = wb + (ch % 3) * BUFSZ;
        const int kb = ch * KC;
#pragma unroll
        for (int k4 = 0; k4 < KC; k4 += 4) {
            float4 av[4];
#pragma unroll
            for (int i = 0; i < 4; i++) av[i] = *(const float4*)&hsm[(r0 + i) * H + kb + k4];
            float ax[4][4];
#pragma unroll
            for (int i = 0; i < 4; i++) {
                ax[i][0] = av[i].x; ax[i][1] = av[i].y; ax[i][2] = av[i].z; ax[i][3] = av[i].w;
            }
#pragma unroll
            for (int kk = 0; kk < 4; kk++) {
                const float* wr = wrb + (k4 + kk) * D;
                ulonglong2 w = *(const ulonglong2*)(wr + c0);
#pragma unroll
                for (int i = 0; i < 4; i++) {
                    ull a2 = pack2(ax[i][kk]);
                    acc[i][0] = fma2(a2, w.x, acc[i][0]);
                    acc[i][1] = fma2(a2, w.y, acc[i][1]);
                }
            }
        }
        if (ch + 2 < NCH) copy_chunk<N4>(wb + ((ch + 2) % 3) * BUFSZ, gW2 + (ch + 2) * KC * D, tid);
        cpcommit();
    }
}

// dst(owned elems) = src + sum_{j<cnt} cf[j]*k_j  (cf includes dt)
__device__ __forceinline__ void combine_store(float* dst, const float* src,
                                              const ull (&kp)[6][4][2],
                                              const float* cf, int cnt,
                                              int r0, int c0) {
    ull cc[6];
#pragma unroll
    for (int j = 0; j < 6; j++) cc[j] = (j < cnt) ? pack2(cf[j]) : 0ULL;
#pragma unroll
    for (int i = 0; i < 4; i++) {
        ulonglong2 yv = *(const ulonglong2*)&src[(r0 + i) * D + c0];
        ull e0 = yv.x, e1 = yv.y;
#pragma unroll
        for (int j = 0; j < 6; j++) {
            if (j < cnt) {
                e0 = fma2(cc[j], kp[j][i][0], e0);
                e1 = fma2(cc[j], kp[j][i][1], e1);
            }
        }
        ulonglong2 o; o.x = e0; o.y = e1;
        *(ulonglong2*)&dst[(r0 + i) * D + c0] = o;
    }
}

__global__ void __launch_bounds__(THREADS, 1)
node_ode_kernel(const float* __restrict__ x0, const float* __restrict__ t,
                const float* __restrict__ W1, const float* __restrict__ b1,
                const float* __restrict__ W2, const float* __restrict__ b2,
                const float* __restrict__ Wc1, const float* __restrict__ bc1,
                const float* __restrict__ Wc2, const float* __restrict__ bc2,
                float* __restrict__ out) {
    extern __shared__ float sm[];
    float* ysm  = sm + OFF_Y;
    float* yssm = sm + OFF_YS;
    float* hsm  = sm + OFF_H;
    float* wb   = sm + OFF_W;

    const int tid = threadIdx.x;
    const int r0 = (tid >> 6) * 4;
    const int c0 = (tid & 63) * 4;
    const int rowBase = blockIdx.x * ROWS;

    {   // load initial y tile
        const float4* src = (const float4*)(x0 + (size_t)rowBase * D);
        float4* dst = (float4*)ysm;
#pragma unroll
        for (int i = 0; i < (ROWS * D / 4) / THREADS; i++)
            dst[tid + i * THREADS] = src[tid + i * THREADS];
    }

    float b1r[8];
    {
        float4 u = *(const float4*)&b1[c0];
        float4 v = *(const float4*)&b1[c0 + 256];
        b1r[0] = u.x; b1r[1] = u.y; b1r[2] = u.z; b1r[3] = u.w;
        b1r[4] = v.x; b1r[5] = v.y; b1r[6] = v.z; b1r[7] = v.w;
    }
    ulonglong2 b2p = *(const ulonglong2*)&b2[c0];

    float tv[TPTS];
#pragma unroll
    for (int i = 0; i < TPTS; i++) tv[i] = t[i];

    __syncthreads();

    // dopri5 tableau: A[s] = coefficients a_{s+1,1..s}; B = 5th-order weights
    const float A1[1] = {0.2f};
    const float A2[2] = {3.0f/40.0f, 9.0f/40.0f};
    const float A3[3] = {44.0f/45.0f, -56.0f/15.0f, 32.0f/9.0f};
    const float A4[4] = {19372.0f/6561.0f, -25360.0f/2187.0f, 64448.0f/6561.0f, -212.0f/729.0f};
    const float A5[5] = {9017.0f/3168.0f, -355.0f/33.0f, 46732.0f/5247.0f, 49.0f/176.0f, -5103.0f/18656.0f};
    const float B6[6] = {35.0f/384.0f, 0.0f, 500.0f/1113.0f, 125.0f/192.0f, -2187.0f/6784.0f, 11.0f/84.0f};
    const float* Arows[5] = {A1, A2, A3, A4, A5};

    ull kp[6][4][2];

    for (int iv = 0; iv < TPTS - 1; iv++) {
        const float dt = (tv[iv + 1] - tv[iv]) * 0.25f;   // SUBSTEPS = 4
        for (int ss = 0; ss < 4; ss++) {
            // stage 1: k1 = f(y)
            gemm1(ysm, W1, hsm, wb, b1r, tid, r0, c0);
            __syncthreads();
            gemm2(hsm, W2, wb, kp[0], b2p, tid, r0, c0);
            // stages 2..6
            for (int s = 1; s < 6; s++) {
                float cf[5];
                for (int j = 0; j < s; j++) cf[j] = dt * Arows[s - 1][j];
                combine_store(yssm, ysm, kp, cf, s, r0, c0);
                __syncthreads();
                gemm1(yssm, W1, hsm, wb, b1r, tid, r0, c0);
                __syncthreads();
                gemm2(hsm, W2, wb, kp[s], b2p, tid, r0, c0);
            }
            // final: y += dt * sum b_i k_i
            float cf[6];
            for (int j = 0; j < 6; j++) cf[j] = dt * B6[j];
            combine_store(ysm, ysm, kp, cf, 6, r0, c0);
            __syncthreads();
        }
    }

    // classifier head: h2 = relu(y @ Wc1 + bc1), [16 x 64] into yssm
    {
        const int r  = tid >> 4;
        const int cc = (tid & 15) * 4;
        float4 bb = *(const float4*)&bc1[cc];
        float a0 = bb.x, a1 = bb.y, a2 = bb.z, a3 = bb.w;
#pragma unroll 4
        for (int k = 0; k < D; k++) {
            float a = ysm[r * D + k];
            float4 w = *(const float4*)&Wc1[k * 64 + cc];
            a0 = fmaf(a, w.x, a0); a1 = fmaf(a, w.y, a1);
            a2 = fmaf(a, w.z, a2); a3 = fmaf(a, w.w, a3);
        }
        float4 o;
        o.x = fmaxf(a0, 0.0f); o.y = fmaxf(a1, 0.0f);
        o.z = fmaxf(a2, 0.0f); o.w = fmaxf(a3, 0.0f);
        *(float4*)&yssm[r * 64 + cc] = o;
    }
    __syncthreads();
    // logits = h2 @ Wc2 + bc2, [16 x 10]
    if (tid < ROWS * NCLS) {
        const int r = tid / NCLS;
        const int c = tid - r * NCLS;
        float s = bc2[c];
#pragma unroll 8
        for (int k = 0; k < 64; k++)
            s = fmaf(yssm[r * 64 + k], Wc2[k * NCLS + c], s);
        out[(size_t)(rowBase + r) * NCLS + c] = s;
    }
}

extern "C" void kernel_launch(void* const* d_in, const int* in_sizes, int n_in,
                              void* d_out, int out_size) {
    const float* x0  = (const float*)d_in[0];
    const float* t   = (const float*)d_in[1];
    const float* W1  = (const float*)d_in[2];
    const float* b1  = (const float*)d_in[3];
    const float* W2  = (const float*)d_in[4];
    const float* b2  = (const float*)d_in[5];
    const float* Wc1 = (const float*)d_in[6];
    const float* bc1 = (const float*)d_in[7];
    const float* Wc2 = (const float*)d_in[8];
    const float* bc2 = (const float*)d_in[9];
    float* out = (float*)d_out;

    static bool attr_set = false;
    if (!attr_set) {
        cudaFuncSetAttribute(node_ode_kernel,
                             cudaFuncAttributeMaxDynamicSharedMemorySize, SMEM_BYTES);
        attr_set = true;
    }
    node_ode_kernel<<<2048 / ROWS, THREADS, SMEM_BYTES>>>(
        x0, t, W1, b1, W2, b2, Wc1, bc1, Wc2, bc2, out);
}